// round 16
// baseline (speedup 1.0000x reference)
#include <cuda_runtime.h>

// SoftRank via bucket-histogram rank + narrow tanh window.
// out[b,j,c] = (1/N) * sum_i sigmoid(1000*(x[b,j,c]-x[b,i,c]))
//
// 512 threads x 2 elements/thread per (b,c) column (one CTA):
//   fewer barrier participants (16 warps), MLP=2 loads, same 1024-lane
//   atomic phase (LSU floor), 8-bucket/thread prefix scan.
//   1. histogram 1024 values into 4096 buckets over [-5,5] (smem atomics)
//   2. block exclusive prefix sum, 8 buckets/thread (2x uint4), all warps
//      redundantly scan the 16 warp totals, sentinel cnt[4096]=N
//   3. scatter values into bucket order
//   4. own-element epilogue: rank = prefix of lower buckets (each exactly 1;
//      aggregate tail err ~3.5e-5, model calibrated over rounds 8-14), plus
//      branchless tanh.approx window scan (saturation keeps out-of-window
//      scanned elements exact).

#define NN       1024
#define CC       16
#define BB       8
#define TPB      512
#define NBKT     4096
#define RANGE_LO (-5.0f)
#define INV_W    409.6f          // NBKT / 10.0
#define WINDOW   0.0025f         // cutoff arg >= 2.5 -> rel err ~3.5e-5

__device__ __forceinline__ float fast_tanh(float x) {
    float r;
    asm("tanh.approx.f32 %0, %1;" : "=f"(r) : "f"(x));
    return r;
}

__device__ __forceinline__ int bucket_of(float v) {
    int b = (int)((v - RANGE_LO) * INV_W);
    return min(max(b, 0), NBKT - 1);
}

__global__ __launch_bounds__(TPB) void softrank_v512_kernel(
    const float* __restrict__ x, float* __restrict__ out)
{
    const int b = blockIdx.x >> 4;       // / CC
    const int c = blockIdx.x & (CC - 1); // % CC

    __shared__ unsigned cnt[NBKT + 4];   // counts -> exclusive prefix; [NBKT]=N sentinel
    __shared__ float    skey[NN];        // values in bucket order
    __shared__ unsigned wsum[16];

    const int t    = threadIdx.x;
    const int lane = t & 31;
    const int wid  = t >> 5;

    // ---- load both elements early (MLP=2) ----
    const int base = (b * NN) * CC + c;
    const float v0 = x[base + t * CC];
    const float v1 = x[base + (t + TPB) * CC];

    // zero 8 buckets per thread
    ((uint4*)cnt)[2 * t]     = make_uint4(0u, 0u, 0u, 0u);
    ((uint4*)cnt)[2 * t + 1] = make_uint4(0u, 0u, 0u, 0u);

    const int bk0 = bucket_of(v0);
    const int bk1 = bucket_of(v1);
    __syncthreads();

    // ---- histogram; slot = within-bucket ordinal ----
    const unsigned slot0 = atomicAdd(&cnt[bk0], 1u);
    const unsigned slot1 = atomicAdd(&cnt[bk1], 1u);
    __syncthreads();

    // ---- block exclusive prefix sum over 4096 counts, 8 per thread ----
    const uint4 a4 = ((uint4*)cnt)[2 * t];
    const uint4 b4 = ((uint4*)cnt)[2 * t + 1];
    const unsigned tsum = a4.x + a4.y + a4.z + a4.w + b4.x + b4.y + b4.z + b4.w;

    unsigned inc = tsum;                 // warp-inclusive scan of thread sums
    #pragma unroll
    for (int j = 1; j < 32; j <<= 1) {
        unsigned n = __shfl_up_sync(0xffffffffu, inc, j);
        if (lane >= j) inc += n;
    }
    if (lane == 31) wsum[wid] = inc;
    __syncthreads();

    // every warp redundantly scans the 16 warp totals (no wid-0 wait)
    unsigned wv = (lane < 16) ? wsum[lane] : 0u;
    unsigned wi = wv;
    #pragma unroll
    for (int j = 1; j < 16; j <<= 1) {
        unsigned n = __shfl_up_sync(0xffffffffu, wi, j);
        if (lane >= j) wi += n;
    }
    const unsigned wexcl = __shfl_sync(0xffffffffu, wi - wv, wid);

    unsigned run = wexcl + (inc - tsum);
    uint4 pa, pb;
    pa.x = run;           run += a4.x;
    pa.y = run;           run += a4.y;
    pa.z = run;           run += a4.z;
    pa.w = run;           run += a4.w;
    pb.x = run;           run += b4.x;
    pb.y = run;           run += b4.y;
    pb.z = run;           run += b4.z;
    pb.w = run;
    ((uint4*)cnt)[2 * t]     = pa;
    ((uint4*)cnt)[2 * t + 1] = pb;
    if (t == 0) cnt[NBKT] = (unsigned)NN;        // branchless end lookup
    __syncthreads();

    // ---- scatter into bucket order ----
    skey[cnt[bk0] + slot0] = v0;
    skey[cnt[bk1] + slot1] = v1;
    __syncthreads();

    // ---- own-element epilogue for both elements ----
    #pragma unroll
    for (int pass = 0; pass < 2; ++pass) {
        const float v   = pass ? v1 : v0;
        const int   row = pass ? (t + TPB) : t;

        const int b_lo = bucket_of(v - WINDOW);
        const int b_hi = bucket_of(v + WINDOW);

        const unsigned start = cnt[b_lo];
        const unsigned end   = cnt[b_hi + 1];

        const float a = 500.0f * v;
        float s0 = 0.0f, s1 = 0.0f;
        unsigned i = start;
        for (; i + 1 < end; i += 2) {    // 2-way ILP on LDS + MUFU
            s0 += fast_tanh(fmaf(-500.0f, skey[i],     a));
            s1 += fast_tanh(fmaf(-500.0f, skey[i + 1], a));
        }
        if (i < end)
            s0 += fast_tanh(fmaf(-500.0f, skey[i], a));

        const float sum = (float)start
                        + 0.5f * (float)(end - start)
                        + 0.5f * (s0 + s1);

        out[base + row * CC] = sum * (1.0f / (float)NN);
    }
}

extern "C" void kernel_launch(void* const* d_in, const int* in_sizes, int n_in,
                              void* d_out, int out_size)
{
    const float* x = (const float*)d_in[0];
    float* out = (float*)d_out;
    softrank_v512_kernel<<<BB * CC, TPB>>>(x, out);
}